// round 3
// baseline (speedup 1.0000x reference)
#include <cuda_runtime.h>

#define NTOK 65536
#define DIM  64
#define KC   4096
#define KSPLIT 4
#define KPER (KC / KSPLIT)   // 1024

// output layout: quantized_st [N*D], loss, perplexity, new_e [D*K], new_cs [K], new_un [D*K]
#define OFF_LOSS 4194304
#define OFF_PERP 4194305
#define OFF_NE   4194306
#define OFF_NCS  4456450
#define OFF_NUN  4460546

typedef unsigned long long ull;

// ---------------- device scratch (no allocations allowed) ----------------
__device__ float g_eT[KC * DIM];        // embeddings transposed [K, D] for coalesced gather
__device__ float g_ee[KC];              // ||e_k||^2
__device__ float g_pval[NTOK * KSPLIT]; // per-split best value
__device__ int   g_pidx[NTOK * KSPLIT]; // per-split best index
__device__ float g_counts[KC];
__device__ float g_sums[KC * DIM];      // per-cluster sum of x, [K, D]
__device__ float g_losspart[NTOK / 4];  // per-block loss partials
__device__ float g_scal[2];             // [0]=n_sum, [1]=entropy_sum

// ---------------- f32x2 helpers ----------------
__device__ __forceinline__ ull dup2(float v) {
    ull r;
    asm("mov.b64 %0, {%1, %1};" : "=l"(r) : "f"(v));
    return r;
}
__device__ __forceinline__ void fma2(ull &acc, ull a, ull b) {
    asm("fma.rn.f32x2 %0, %1, %2, %0;" : "+l"(acc) : "l"(a), "l"(b));
}
__device__ __forceinline__ float2 unpack2(ull v) {
    float lo, hi;
    asm("mov.b64 {%0, %1}, %2;" : "=f"(lo), "=f"(hi) : "l"(v));
    return make_float2(lo, hi);
}

// ---------------- kernel 1: prep (||e||^2, transpose) + zero scratch ----------------
__global__ void prep_kernel(const float* __restrict__ e) {
    int k = blockIdx.x * blockDim.x + threadIdx.x;
    float s = 0.f;
    #pragma unroll
    for (int d = 0; d < DIM; d++) {
        float v = e[d * KC + k];
        g_eT[k * DIM + d] = v;
        g_sums[k * DIM + d] = 0.f;
        s = fmaf(v, v, s);
    }
    g_ee[k] = s;
    g_counts[k] = 0.f;
    if (k < 2) g_scal[k] = 0.f;
}

// ---------------- kernel 2: fused distance GEMM + partial argmin (split-K) ----------
// CTA tile: 128 tokens x 128 codes per iteration, over a 1024-code K-split.
// 256 threads, micro-tile 4 tokens x 16 codes, f32x2-packed accumulation.
// b-operand pairs come directly out of LDS.128 (ulonglong2) -> zero pack MOVs.
#define BM 128
#define BN 128

__global__ __launch_bounds__(256, 2) void argmin_kernel(const float* __restrict__ x,
                                                        const float* __restrict__ e) {
    __shared__ float As[DIM][BM];   // 32 KB, d-major (transposed x tile)
    __shared__ float Bs[DIM][BN];   // 32 KB
    const int tid  = threadIdx.x;
    const int m0   = blockIdx.x * BM;
    const int kbeg = blockIdx.y * KPER;
    const int tx   = tid & 7;        // 8 code groups (16 codes each)
    const int ty   = tid >> 3;       // 32 token groups (4 tokens each)

    // load A tile transposed (one-time): 128 tokens x 64 d = 2048 float4
    #pragma unroll
    for (int i = 0; i < 8; i++) {
        int lin = tid + i * 256;
        int r = lin >> 4;
        int c = (lin & 15) << 2;
        float4 v = *reinterpret_cast<const float4*>(&x[(m0 + r) * DIM + c]);
        As[c + 0][r] = v.x; As[c + 1][r] = v.y; As[c + 2][r] = v.z; As[c + 3][r] = v.w;
    }

    float best[4] = {3.0e38f, 3.0e38f, 3.0e38f, 3.0e38f};
    int   bidx[4] = {0, 0, 0, 0};

    for (int k0 = kbeg; k0 < kbeg + KPER; k0 += BN) {
        __syncthreads();
        #pragma unroll
        for (int i = 0; i < 8; i++) {
            int lin = tid + i * 256;        // 2048 float4
            int d = lin >> 5;
            int c = (lin & 31) << 2;
            *reinterpret_cast<float4*>(&Bs[d][c]) =
                *reinterpret_cast<const float4*>(&e[d * KC + k0 + c]);
        }
        __syncthreads();

        // acc[i][p]: token ty*4+i, code pair p -> codes tx*16 + 2p, 2p+1
        ull acc[4][8];
        #pragma unroll
        for (int i = 0; i < 4; i++)
            #pragma unroll
            for (int p = 0; p < 8; p++) acc[i][p] = 0ULL;

        #pragma unroll 4
        for (int d = 0; d < DIM; d++) {
            float4 av = *reinterpret_cast<const float4*>(&As[d][ty * 4]);
            ull a[4];
            a[0] = dup2(av.x); a[1] = dup2(av.y); a[2] = dup2(av.z); a[3] = dup2(av.w);
            // 16 codes = 4 x LDS.128, halves are ready-made f32x2 pairs
            ulonglong2 q0 = *reinterpret_cast<const ulonglong2*>(&Bs[d][tx * 16]);
            ulonglong2 q1 = *reinterpret_cast<const ulonglong2*>(&Bs[d][tx * 16 + 4]);
            ulonglong2 q2 = *reinterpret_cast<const ulonglong2*>(&Bs[d][tx * 16 + 8]);
            ulonglong2 q3 = *reinterpret_cast<const ulonglong2*>(&Bs[d][tx * 16 + 12]);
            ull bp[8] = {q0.x, q0.y, q1.x, q1.y, q2.x, q2.y, q3.x, q3.y};
            #pragma unroll
            for (int i = 0; i < 4; i++)
                #pragma unroll
                for (int p = 0; p < 8; p++)
                    fma2(acc[i][p], a[i], bp[p]);
        }

        // epilogue: score = ||e||^2 - 2 x.e ; running argmin (ascending k, strict <)
        #pragma unroll
        for (int p = 0; p < 8; p++) {
            int kbase = k0 + tx * 16 + 2 * p;
            float2 ee = *reinterpret_cast<const float2*>(&g_ee[kbase]);
            #pragma unroll
            for (int i = 0; i < 4; i++) {
                float2 s = unpack2(acc[i][p]);
                float s0 = fmaf(-2.f, s.x, ee.x);
                float s1 = fmaf(-2.f, s.y, ee.y);
                if (s0 < best[i]) { best[i] = s0; bidx[i] = kbase; }
                if (s1 < best[i]) { best[i] = s1; bidx[i] = kbase + 1; }
            }
        }
    }

    // reduce across the 8 tx threads of each token group (8-lane segments)
    #pragma unroll
    for (int i = 0; i < 4; i++) {
        float v = best[i];
        int   id = bidx[i];
        #pragma unroll
        for (int off = 4; off > 0; off >>= 1) {
            float v2 = __shfl_down_sync(0xffffffffu, v, off, 8);
            int  id2 = __shfl_down_sync(0xffffffffu, id, off, 8);
            if (v2 < v || (v2 == v && id2 < id)) { v = v2; id = id2; }
        }
        if (tx == 0) {
            int tok = m0 + ty * 4 + i;
            g_pval[tok * KSPLIT + blockIdx.y] = v;
            g_pidx[tok * KSPLIT + blockIdx.y] = id;
        }
    }
}

// ---------------- kernel 3: combine + gather/quantize + loss + EMA scatter --------
__global__ __launch_bounds__(256) void quant_kernel(const float* __restrict__ x,
                                                    float* __restrict__ out) {
    int t   = threadIdx.x;
    int tok = blockIdx.x * 4 + (t >> 6);
    int d   = t & 63;
    // inline split-K combine (ascending split order => first-min tiebreak)
    int base = tok * KSPLIT;
    float bv = g_pval[base];
    int  idx = g_pidx[base];
    #pragma unroll
    for (int s = 1; s < KSPLIT; s++) {
        float v2 = g_pval[base + s];
        int  id2 = g_pidx[base + s];
        if (v2 < bv) { bv = v2; idx = id2; }
    }
    float xv = x[tok * DIM + d];
    float q  = g_eT[idx * DIM + d];
    out[tok * DIM + d] = xv + (q - xv);          // straight-through, ref arithmetic
    float diff = q - xv;
    float l = diff * diff;
    #pragma unroll
    for (int off = 16; off; off >>= 1) l += __shfl_down_sync(0xffffffffu, l, off);
    __shared__ float part[8];
    if ((t & 31) == 0) part[t >> 5] = l;
    if (d == 0) atomicAdd(&g_counts[idx], 1.0f);
    atomicAdd(&g_sums[idx * DIM + d], xv);
    __syncthreads();
    if (t == 0) {
        float s = 0.f;
        #pragma unroll
        for (int w = 0; w < 8; w++) s += part[w];
        g_losspart[blockIdx.x] = s;
    }
}

// ---------------- kernel 4: loss reduction ----------------
__global__ void loss_kernel(float* __restrict__ out) {
    int t = threadIdx.x;
    float s = 0.f;
    for (int i = t; i < NTOK / 4; i += 256) s += g_losspart[i];
    #pragma unroll
    for (int off = 16; off; off >>= 1) s += __shfl_down_sync(0xffffffffu, s, off);
    __shared__ float part[8];
    if ((t & 31) == 0) part[t >> 5] = s;
    __syncthreads();
    if (t == 0) {
        float tt = 0.f;
        #pragma unroll
        for (int w = 0; w < 8; w++) tt += part[w];
        out[OFF_LOSS] = tt * (0.25f / (float)(NTOK * DIM));
    }
}

// ---------------- kernel 5: new_cs + reductions for n and entropy ----------------
__global__ __launch_bounds__(256) void newcs_kernel(const float* __restrict__ cs,
                                                    float* __restrict__ out) {
    int t = threadIdx.x;
    int k = blockIdx.x * 256 + t;
    float cnt = g_counts[k];
    float ncs = 0.1f * cnt + 0.9f * cs[k];
    out[OFF_NCS + k] = ncs;
    float avg = cnt * (1.0f / (float)NTOK);
    float ent = avg * logf(avg + 1e-20f);
    #pragma unroll
    for (int off = 16; off; off >>= 1) {
        ncs += __shfl_down_sync(0xffffffffu, ncs, off);
        ent += __shfl_down_sync(0xffffffffu, ent, off);
    }
    __shared__ float p1[8], p2[8];
    if ((t & 31) == 0) { p1[t >> 5] = ncs; p2[t >> 5] = ent; }
    __syncthreads();
    if (t == 0) {
        float s1 = 0.f, s2 = 0.f;
        #pragma unroll
        for (int w = 0; w < 8; w++) { s1 += p1[w]; s2 += p2[w]; }
        atomicAdd(&g_scal[0], s1);
        atomicAdd(&g_scal[1], s2);
    }
}

// ---------------- kernel 6: new_un, new_e, perplexity ----------------
__global__ __launch_bounds__(256) void final_kernel(const float* __restrict__ cs,
                                                    const float* __restrict__ un,
                                                    float* __restrict__ out) {
    int lin = blockIdx.x * 256 + threadIdx.x;   // 0..262143 over [D, K]
    int d = lin >> 12;
    int k = lin & (KC - 1);
    float nun = 0.1f * g_sums[k * DIM + d] + 0.9f * un[lin];
    out[OFF_NUN + lin] = nun;
    float n   = g_scal[0];
    float ncs = 0.1f * g_counts[k] + 0.9f * cs[k];
    float stable = (ncs + 1e-20f) / (n + 4.096e-17f) * n;
    out[OFF_NE + lin] = nun / stable;
    if (lin == 0) out[OFF_PERP] = expf(-g_scal[1]);
}

// ---------------- launch ----------------
extern "C" void kernel_launch(void* const* d_in, const int* in_sizes, int n_in,
                              void* d_out, int out_size) {
    const float* x  = (const float*)d_in[0];   // [N, D]
    const float* e  = (const float*)d_in[1];   // [D, K]
    const float* cs = (const float*)d_in[2];   // [K]
    const float* un = (const float*)d_in[3];   // [D, K]
    float* out = (float*)d_out;

    prep_kernel<<<KC / 256, 256>>>(e);
    dim3 agrid(NTOK / BM, KSPLIT);
    argmin_kernel<<<agrid, 256>>>(x, e);
    quant_kernel<<<NTOK / 4, 256>>>(x, out);
    loss_kernel<<<1, 256>>>(out);
    newcs_kernel<<<KC / 256, 256>>>(cs, out);
    final_kernel<<<DIM * KC / 256, 256>>>(cs, un, out);
}

// round 4
// speedup vs baseline: 2.6729x; 2.6729x over previous
#include <cuda_runtime.h>

#define NTOK 65536
#define DIM  64
#define KC   4096
#define KSPLIT 4
#define KPER (KC / KSPLIT)   // 1024

// output layout: quantized_st [N*D], loss, perplexity, new_e [D*K], new_cs [K], new_un [D*K]
#define OFF_LOSS 4194304
#define OFF_PERP 4194305
#define OFF_NE   4194306
#define OFF_NCS  4456450
#define OFF_NUN  4460546

typedef unsigned long long ull;

// ---------------- device scratch (no allocations allowed) ----------------
__device__ float g_eT[KC * DIM];        // embeddings transposed [K, D] for coalesced gather
__device__ float g_ee[KC];              // ||e_k||^2
__device__ float g_pval[NTOK * KSPLIT]; // per-split best value
__device__ int   g_pidx[NTOK * KSPLIT]; // per-split best index
__device__ float g_counts[KC];
__device__ float g_sums[KC * DIM];      // per-cluster sum of x, [K, D]
__device__ float g_losspart[NTOK / 4];  // per-block loss partials
__device__ float g_scal[2];             // [0]=n_sum, [1]=entropy_sum

// ---------------- f32x2 helpers ----------------
__device__ __forceinline__ ull dup2(float v) {
    ull r;
    asm("mov.b64 %0, {%1, %1};" : "=l"(r) : "f"(v));
    return r;
}
__device__ __forceinline__ void fma2(ull &acc, ull a, ull b) {
    asm("fma.rn.f32x2 %0, %1, %2, %0;" : "+l"(acc) : "l"(a), "l"(b));
}
__device__ __forceinline__ float2 unpack2(ull v) {
    float lo, hi;
    asm("mov.b64 {%0, %1}, %2;" : "=f"(lo), "=f"(hi) : "l"(v));
    return make_float2(lo, hi);
}

// ---------------- kernel 1: prep (||e||^2, transpose) + zero scratch ----------------
__global__ void prep_kernel(const float* __restrict__ e) {
    int k = blockIdx.x * blockDim.x + threadIdx.x;
    float s = 0.f;
    #pragma unroll
    for (int d = 0; d < DIM; d++) {
        float v = e[d * KC + k];
        g_eT[k * DIM + d] = v;
        g_sums[k * DIM + d] = 0.f;
        s = fmaf(v, v, s);
    }
    g_ee[k] = s;
    g_counts[k] = 0.f;
    if (k < 2) g_scal[k] = 0.f;
}

// ---------------- kernel 2: fused distance GEMM + partial argmin (split-K) ----------
// CTA tile: 64 tokens x 128 codes per iteration, over a 1024-code K-split.
// 256 threads, micro-tile 4 tokens x 8 codes.
// b-pairs come DIRECTLY out of LDS.128 as ulonglong2 (zero pack MOVs);
// codes at tx*4 / 64+tx*4 keep all LDS.128 reads on consecutive 16B granules
// (conflict-free with 16-thread span + broadcast).
#define BM 64
#define BN 128

__global__ __launch_bounds__(256, 3) void argmin_kernel(const float* __restrict__ x,
                                                        const float* __restrict__ e) {
    __shared__ float As[DIM][BM];   // 16 KB, d-major (transposed x tile)
    __shared__ float Bs[DIM][BN];   // 32 KB
    const int tid  = threadIdx.x;
    const int m0   = blockIdx.x * BM;
    const int kbeg = blockIdx.y * KPER;
    const int tx   = tid & 15;       // 16 code groups
    const int ty   = tid >> 4;       // 16 token groups (4 tokens each)

    // load A tile transposed (one-time)
    #pragma unroll
    for (int i = 0; i < 4; i++) {
        int lin = tid + i * 256;            // float4 index, 1024 total
        int r = lin >> 4;
        int c = (lin & 15) << 2;
        float4 v = *reinterpret_cast<const float4*>(&x[(m0 + r) * DIM + c]);
        As[c + 0][r] = v.x; As[c + 1][r] = v.y; As[c + 2][r] = v.z; As[c + 3][r] = v.w;
    }

    float best[4] = {3.0e38f, 3.0e38f, 3.0e38f, 3.0e38f};
    int   bidx[4] = {0, 0, 0, 0};

    for (int k0 = kbeg; k0 < kbeg + KPER; k0 += BN) {
        __syncthreads();
        #pragma unroll
        for (int i = 0; i < 8; i++) {
            int lin = tid + i * 256;        // 2048 float4
            int d = lin >> 5;
            int c = (lin & 31) << 2;
            *reinterpret_cast<float4*>(&Bs[d][c]) =
                *reinterpret_cast<const float4*>(&e[d * KC + k0 + c]);
        }
        __syncthreads();

        // acc[i][p]: token ty*4+i; pairs p=0,1 -> codes tx*4+{0..3};
        // p=2,3 -> codes 64+tx*4+{0..3}
        ull acc[4][4];
        #pragma unroll
        for (int i = 0; i < 4; i++)
            #pragma unroll
            for (int p = 0; p < 4; p++) acc[i][p] = 0ULL;

        #pragma unroll 8
        for (int d = 0; d < DIM; d++) {
            float4 av = *reinterpret_cast<const float4*>(&As[d][ty * 4]);
            ull a[4];
            a[0] = dup2(av.x); a[1] = dup2(av.y); a[2] = dup2(av.z); a[3] = dup2(av.w);
            // b-pairs straight from LDS.128 register pairs (no pack MOVs)
            ulonglong2 q0 = *reinterpret_cast<const ulonglong2*>(&Bs[d][tx * 4]);
            ulonglong2 q1 = *reinterpret_cast<const ulonglong2*>(&Bs[d][64 + tx * 4]);
            ull bp[4] = {q0.x, q0.y, q1.x, q1.y};
            #pragma unroll
            for (int i = 0; i < 4; i++)
                #pragma unroll
                for (int p = 0; p < 4; p++)
                    fma2(acc[i][p], a[i], bp[p]);
        }

        // epilogue: score = ||e||^2 - 2 x.e ; running argmin (ascending k, strict <)
        #pragma unroll
        for (int p = 0; p < 4; p++) {
            int kbase = k0 + ((p < 2) ? (tx * 4 + p * 2) : (64 + tx * 4 + (p - 2) * 2));
            float2 ee = *reinterpret_cast<const float2*>(&g_ee[kbase]);
            #pragma unroll
            for (int i = 0; i < 4; i++) {
                float2 s = unpack2(acc[i][p]);
                float s0 = fmaf(-2.f, s.x, ee.x);
                float s1 = fmaf(-2.f, s.y, ee.y);
                if (s0 < best[i]) { best[i] = s0; bidx[i] = kbase; }
                if (s1 < best[i]) { best[i] = s1; bidx[i] = kbase + 1; }
            }
        }
    }

    // reduce across the 16 tx threads of each token group (16-lane segments)
    #pragma unroll
    for (int i = 0; i < 4; i++) {
        float v = best[i];
        int   id = bidx[i];
        #pragma unroll
        for (int off = 8; off > 0; off >>= 1) {
            float v2 = __shfl_down_sync(0xffffffffu, v, off, 16);
            int  id2 = __shfl_down_sync(0xffffffffu, id, off, 16);
            if (v2 < v || (v2 == v && id2 < id)) { v = v2; id = id2; }
        }
        if (tx == 0) {
            int tok = m0 + ty * 4 + i;
            g_pval[tok * KSPLIT + blockIdx.y] = v;
            g_pidx[tok * KSPLIT + blockIdx.y] = id;
        }
    }
}

// ---------------- kernel 3: combine + gather/quantize + loss + EMA scatter --------
__global__ __launch_bounds__(256) void quant_kernel(const float* __restrict__ x,
                                                    float* __restrict__ out) {
    int t   = threadIdx.x;
    int tok = blockIdx.x * 4 + (t >> 6);
    int d   = t & 63;
    // inline split-K combine (ascending split order => first-min tiebreak)
    int base = tok * KSPLIT;
    float bv = g_pval[base];
    int  idx = g_pidx[base];
    #pragma unroll
    for (int s = 1; s < KSPLIT; s++) {
        float v2 = g_pval[base + s];
        int  id2 = g_pidx[base + s];
        if (v2 < bv) { bv = v2; idx = id2; }
    }
    float xv = x[tok * DIM + d];
    float q  = g_eT[idx * DIM + d];
    out[tok * DIM + d] = xv + (q - xv);          // straight-through, ref arithmetic
    float diff = q - xv;
    float l = diff * diff;
    #pragma unroll
    for (int off = 16; off; off >>= 1) l += __shfl_down_sync(0xffffffffu, l, off);
    __shared__ float part[8];
    if ((t & 31) == 0) part[t >> 5] = l;
    if (d == 0) atomicAdd(&g_counts[idx], 1.0f);
    atomicAdd(&g_sums[idx * DIM + d], xv);
    __syncthreads();
    if (t == 0) {
        float s = 0.f;
        #pragma unroll
        for (int w = 0; w < 8; w++) s += part[w];
        g_losspart[blockIdx.x] = s;
    }
}

// ---------------- kernel 4: loss reduction ----------------
__global__ void loss_kernel(float* __restrict__ out) {
    int t = threadIdx.x;
    float s = 0.f;
    for (int i = t; i < NTOK / 4; i += 256) s += g_losspart[i];
    #pragma unroll
    for (int off = 16; off; off >>= 1) s += __shfl_down_sync(0xffffffffu, s, off);
    __shared__ float part[8];
    if ((t & 31) == 0) part[t >> 5] = s;
    __syncthreads();
    if (t == 0) {
        float tt = 0.f;
        #pragma unroll
        for (int w = 0; w < 8; w++) tt += part[w];
        out[OFF_LOSS] = tt * (0.25f / (float)(NTOK * DIM));
    }
}

// ---------------- kernel 5: new_cs + reductions for n and entropy ----------------
__global__ __launch_bounds__(256) void newcs_kernel(const float* __restrict__ cs,
                                                    float* __restrict__ out) {
    int t = threadIdx.x;
    int k = blockIdx.x * 256 + t;
    float cnt = g_counts[k];
    float ncs = 0.1f * cnt + 0.9f * cs[k];
    out[OFF_NCS + k] = ncs;
    float avg = cnt * (1.0f / (float)NTOK);
    float ent = avg * logf(avg + 1e-20f);
    #pragma unroll
    for (int off = 16; off; off >>= 1) {
        ncs += __shfl_down_sync(0xffffffffu, ncs, off);
        ent += __shfl_down_sync(0xffffffffu, ent, off);
    }
    __shared__ float p1[8], p2[8];
    if ((t & 31) == 0) { p1[t >> 5] = ncs; p2[t >> 5] = ent; }
    __syncthreads();
    if (t == 0) {
        float s1 = 0.f, s2 = 0.f;
        #pragma unroll
        for (int w = 0; w < 8; w++) { s1 += p1[w]; s2 += p2[w]; }
        atomicAdd(&g_scal[0], s1);
        atomicAdd(&g_scal[1], s2);
    }
}

// ---------------- kernel 6: new_un, new_e, perplexity ----------------
__global__ __launch_bounds__(256) void final_kernel(const float* __restrict__ cs,
                                                    const float* __restrict__ un,
                                                    float* __restrict__ out) {
    int lin = blockIdx.x * 256 + threadIdx.x;   // 0..262143 over [D, K]
    int d = lin >> 12;
    int k = lin & (KC - 1);
    float nun = 0.1f * g_sums[k * DIM + d] + 0.9f * un[lin];
    out[OFF_NUN + lin] = nun;
    float n   = g_scal[0];
    float ncs = 0.1f * g_counts[k] + 0.9f * cs[k];
    float stable = (ncs + 1e-20f) / (n + 4.096e-17f) * n;
    out[OFF_NE + lin] = nun / stable;
    if (lin == 0) out[OFF_PERP] = expf(-g_scal[1]);
}

// ---------------- launch ----------------
extern "C" void kernel_launch(void* const* d_in, const int* in_sizes, int n_in,
                              void* d_out, int out_size) {
    const float* x  = (const float*)d_in[0];   // [N, D]
    const float* e  = (const float*)d_in[1];   // [D, K]
    const float* cs = (const float*)d_in[2];   // [K]
    const float* un = (const float*)d_in[3];   // [D, K]
    float* out = (float*)d_out;

    prep_kernel<<<KC / 256, 256>>>(e);
    dim3 agrid(NTOK / BM, KSPLIT);
    argmin_kernel<<<agrid, 256>>>(x, e);
    quant_kernel<<<NTOK / 4, 256>>>(x, out);
    loss_kernel<<<1, 256>>>(out);
    newcs_kernel<<<KC / 256, 256>>>(cs, out);
    final_kernel<<<DIM * KC / 256, 256>>>(cs, un, out);
}

// round 6
// speedup vs baseline: 2.8633x; 1.0712x over previous
#include <cuda_runtime.h>
#include <cuda_bf16.h>
#include <cstdint>

#define NTOK 65536
#define DIM  64
#define KC   4096
#define K2   128          // GEMM K: [xhi|xlo] x [bhi|bhi]
#define NKS  8            // 128/16
#define TM   128          // CTA token tile
#define TN   128          // code tile
#define NT   (KC / TN)    // 32
#define MARGIN 0.8f

// output layout: quantized_st [N*D], loss, perplexity, new_e [D*K], new_cs [K], new_un [D*K]
#define OFF_LOSS 4194304
#define OFF_PERP 4194305
#define OFF_NE   4194306
#define OFF_NCS  4456450
#define OFF_NUN  4460546

typedef unsigned long long ull;

// ---------------- device scratch ----------------
__device__ __nv_bfloat16 g_abf[NTOK * K2];   // 16 MB  [tok][xhi(64)|xlo(64)]
__device__ __nv_bfloat16 g_bbf[KC * K2];     // 1 MB   [code][bhi(64)|bhi(64)], b=-2e
__device__ float g_eT[KC * DIM];
__device__ float g_ee[KC];
__device__ int   g_idx[NTOK];
__device__ int   g_amb[NTOK];
__device__ int   g_ambcnt;
__device__ float g_counts[KC];
__device__ float g_sums[KC * DIM];
__device__ float g_losspart[NTOK / 4];
__device__ float g_scal[2];

// ---------------- helpers ----------------
__device__ __forceinline__ uint32_t smem_u32(const void* p) {
    uint32_t a;
    asm("{ .reg .u64 t; cvta.to.shared.u64 t, %1; cvt.u32.u64 %0, t; }" : "=r"(a) : "l"(p));
    return a;
}
__device__ __forceinline__ void ldm4(uint32_t* r, uint32_t addr) {
    asm volatile("ldmatrix.sync.aligned.m8n8.x4.shared.b16 {%0,%1,%2,%3}, [%4];"
        : "=r"(r[0]), "=r"(r[1]), "=r"(r[2]), "=r"(r[3]) : "r"(addr));
}
__device__ __forceinline__ void mma_acc(float* c, const uint32_t* a, const uint32_t* b) {
    asm volatile("mma.sync.aligned.m16n8k16.row.col.f32.bf16.bf16.f32 "
        "{%0,%1,%2,%3}, {%4,%5,%6,%7}, {%8,%9}, {%0,%1,%2,%3};"
        : "+f"(c[0]), "+f"(c[1]), "+f"(c[2]), "+f"(c[3])
        : "r"(a[0]), "r"(a[1]), "r"(a[2]), "r"(a[3]), "r"(b[0]), "r"(b[1]));
}
__device__ __forceinline__ void mma_zero(float* c, const uint32_t* a, const uint32_t* b) {
    asm volatile("mma.sync.aligned.m16n8k16.row.col.f32.bf16.bf16.f32 "
        "{%0,%1,%2,%3}, {%4,%5,%6,%7}, {%8,%9}, {%10,%10,%10,%10};"
        : "=f"(c[0]), "=f"(c[1]), "=f"(c[2]), "=f"(c[3])
        : "r"(a[0]), "r"(a[1]), "r"(a[2]), "r"(a[3]), "r"(b[0]), "r"(b[1]), "f"(0.0f));
}
// f32x2 (cleanup kernel)
__device__ __forceinline__ ull dup2(float v) {
    ull r; asm("mov.b64 %0, {%1, %1};" : "=l"(r) : "f"(v)); return r;
}
__device__ __forceinline__ void fma2(ull &acc, ull a, ull b) {
    asm("fma.rn.f32x2 %0, %1, %2, %0;" : "+l"(acc) : "l"(a), "l"(b));
}
__device__ __forceinline__ float2 unpack2(ull v) {
    float lo, hi; asm("mov.b64 {%0, %1}, %2;" : "=f"(lo), "=f"(hi) : "l"(v));
    return make_float2(lo, hi);
}

// smem layout of coarse kernel (padded rows: 128 bf16 = 256B -> 272B stride, conflict-free ldmatrix)
#define ROWB 272
#define A_OFF 0
#define B_OFF 34816
#define EE_OFF 69632
#define RED_OFF 70144
#define SMEM_DYN 72192

// ---------------- prep: split x into bf16 [hi|lo] ----------------
__global__ void prep_x_kernel(const float* __restrict__ x) {
    int idx = blockIdx.x * 256 + threadIdx.x;   // over NTOK*16 float4
    int tok = idx >> 4;
    int d4  = (idx & 15) << 2;
    float4 v = *reinterpret_cast<const float4*>(&x[tok * DIM + d4]);
    __nv_bfloat16 h0 = __float2bfloat16(v.x), h1 = __float2bfloat16(v.y);
    __nv_bfloat16 h2 = __float2bfloat16(v.z), h3 = __float2bfloat16(v.w);
    __nv_bfloat16 l0 = __float2bfloat16(v.x - __bfloat162float(h0));
    __nv_bfloat16 l1 = __float2bfloat16(v.y - __bfloat162float(h1));
    __nv_bfloat16 l2 = __float2bfloat16(v.z - __bfloat162float(h2));
    __nv_bfloat16 l3 = __float2bfloat16(v.w - __bfloat162float(h3));
    __nv_bfloat162* hp = reinterpret_cast<__nv_bfloat162*>(&g_abf[tok * K2 + d4]);
    hp[0] = __nv_bfloat162(h0, h1); hp[1] = __nv_bfloat162(h2, h3);
    __nv_bfloat162* lp = reinterpret_cast<__nv_bfloat162*>(&g_abf[tok * K2 + 64 + d4]);
    lp[0] = __nv_bfloat162(l0, l1); lp[1] = __nv_bfloat162(l2, l3);
}

// ---------------- prep: e -> eT, ee, bf16(-2e) duplicated, zero scratch ----------
__global__ void prep_e_kernel(const float* __restrict__ e) {
    int k = blockIdx.x * blockDim.x + threadIdx.x;
    float s = 0.f;
    __nv_bfloat16* row = &g_bbf[k * K2];
    #pragma unroll 8
    for (int d = 0; d < DIM; d++) {
        float v = e[d * KC + k];
        g_eT[k * DIM + d] = v;
        g_sums[k * DIM + d] = 0.f;
        s = fmaf(v, v, s);
        __nv_bfloat16 bh = __float2bfloat16(-2.f * v);
        row[d] = bh; row[64 + d] = bh;
    }
    g_ee[k] = s;
    g_counts[k] = 0.f;
    if (k < 2) g_scal[k] = 0.f;
    if (k == 0) g_ambcnt = 0;
}

// ---------------- coarse: bf16 mma.sync distance GEMM + packed argmin ----------
// 128 threads = 4 warps (2x2). Warp tile 64x64, mma m16n8k16, mf=4, nf=8.
__global__ void __launch_bounds__(128) coarse_kernel() {
    extern __shared__ __align__(16) char sm[];
    const uint32_t sb = smem_u32(sm);
    const int tid  = threadIdx.x;
    const int wid  = tid >> 5;
    const int lane = tid & 31;
    const int wm   = wid >> 1;      // 0,1: token half
    const int wn   = wid & 1;       // 0,1: code half
    const int m0   = blockIdx.x * TM;
    float* ee_s = reinterpret_cast<float*>(sm + EE_OFF);
    int*   red  = reinterpret_cast<int*>(sm + RED_OFF);

    // A tile load: 128 rows x 128 bf16, padded rows (16B chunks)
    #pragma unroll
    for (int i = 0; i < 16; i++) {
        int lin = tid + i * 128;            // 2048 uint4
        int row = lin >> 4;
        int c16 = lin & 15;
        uint4 v = *reinterpret_cast<const uint4*>(&g_abf[(m0 + row) * K2 + c16 * 8]);
        *reinterpret_cast<uint4*>(sm + A_OFF + row * ROWB + c16 * 16) = v;
    }

    // ldmatrix lane-address bases
    const uint32_t a_base = sb + A_OFF + (wm * 64 + (lane & 15)) * ROWB + (lane & 16);
    const uint32_t b_base = sb + B_OFF + (wn * 64 + ((lane & 7) + ((lane & 16) >> 1))) * ROWB
                            + ((lane & 8) << 1);

    int pk1[8], pk2[8];
    #pragma unroll
    for (int r = 0; r < 8; r++) { pk1[r] = 0x7FFFFFFF; pk2[r] = 0x7FFFFFFF; }

    const int cbl = wn * 64 + (lane & 3) * 2;   // thread's local col base

    #pragma unroll 1
    for (int nt = 0; nt < NT; nt++) {
        __syncthreads();
        // B tile load
        #pragma unroll
        for (int i = 0; i < 16; i++) {
            int lin = tid + i * 128;
            int row = lin >> 4;
            int c16 = lin & 15;
            uint4 v = *reinterpret_cast<const uint4*>(&g_bbf[(nt * TN + row) * K2 + c16 * 8]);
            *reinterpret_cast<uint4*>(sm + B_OFF + row * ROWB + c16 * 16) = v;
        }
        ee_s[tid] = g_ee[nt * TN + tid];
        __syncthreads();

        float acc[4][8][4];
        #pragma unroll
        for (int ks = 0; ks < NKS; ks++) {
            uint32_t af[4][4], bq[4][4];
            #pragma unroll
            for (int mf = 0; mf < 4; mf++) ldm4(af[mf], a_base + mf * (16 * ROWB) + ks * 32);
            #pragma unroll
            for (int q = 0; q < 4; q++)    ldm4(bq[q], b_base + q * (16 * ROWB) + ks * 32);
            #pragma unroll
            for (int mf = 0; mf < 4; mf++)
                #pragma unroll
                for (int nf = 0; nf < 8; nf++) {
                    const uint32_t* b = &bq[nf >> 1][(nf & 1) * 2];
                    if (ks == 0) mma_zero(acc[mf][nf], af[mf], b);
                    else         mma_acc(acc[mf][nf], af[mf], b);
                }
        }

        // epilogue: packed (score|idx) min + second-min
        const int kb = nt * TN + cbl;
        #pragma unroll
        for (int nf = 0; nf < 8; nf++) {
            float ee0 = ee_s[cbl + nf * 8];
            float ee1 = ee_s[cbl + nf * 8 + 1];
            int k0 = kb + nf * 8, k1 = k0 + 1;
            #pragma unroll
            for (int mf = 0; mf < 4; mf++) {
                #pragma unroll
                for (int h = 0; h < 2; h++) {
                    int r = 2 * mf + h;
                    float v0 = acc[mf][nf][2 * h + 0] + ee0;
                    float v1 = acc[mf][nf][2 * h + 1] + ee1;
                    int p0 = (__float_as_int(v0) & 0xFFFFF000) | k0;
                    int t0 = max(pk1[r], p0);
                    pk1[r] = min(pk1[r], p0);
                    pk2[r] = min(pk2[r], t0);
                    int p1 = (__float_as_int(v1) & 0xFFFFF000) | k1;
                    int t1 = max(pk1[r], p1);
                    pk1[r] = min(pk1[r], p1);
                    pk2[r] = min(pk2[r], t1);
                }
            }
        }
    }

    // reduce across the 4 lanes sharing each row (lane bits 0-1)
    #pragma unroll
    for (int r = 0; r < 8; r++) {
        #pragma unroll
        for (int m = 1; m <= 2; m <<= 1) {
            int q1 = __shfl_xor_sync(0xffffffffu, pk1[r], m);
            int q2 = __shfl_xor_sync(0xffffffffu, pk2[r], m);
            int t  = max(pk1[r], q1);
            pk1[r] = min(pk1[r], q1);
            pk2[r] = min(min(pk2[r], q2), t);
        }
    }
    __syncthreads();
    if ((lane & 3) == 0) {
        #pragma unroll
        for (int r = 0; r < 8; r++) {
            int row = wm * 64 + (r >> 1) * 16 + (lane >> 2) + (r & 1) * 8;
            red[row * 4 + wn * 2 + 0] = pk1[r];
            red[row * 4 + wn * 2 + 1] = pk2[r];
        }
    }
    __syncthreads();
    // final cross-wn merge, one thread per token
    {
        int row = tid;
        int p1a = red[row * 4 + 0], p2a = red[row * 4 + 1];
        int p1b = red[row * 4 + 2], p2b = red[row * 4 + 3];
        int t  = max(p1a, p1b);
        int p1 = min(p1a, p1b);
        int p2 = min(min(p2a, p2b), t);
        int tok = m0 + row;
        g_idx[tok] = p1 & 0xFFF;
        float f1 = __int_as_float(p1 & 0xFFFFF000);
        float f2 = __int_as_float(p2 & 0xFFFFF000);
        if (f2 - f1 < MARGIN) {
            int pos = atomicAdd(&g_ambcnt, 1);
            g_amb[pos] = tok;
        }
    }
}

// ---------------- cleanup: exact fp32 (f32x2) rescan of ambiguous tokens --------
#define CBM 32
__global__ __launch_bounds__(256) void cleanup_kernel(const float* __restrict__ x,
                                                      const float* __restrict__ e) {
    __shared__ float As[DIM][CBM];    // 8 KB
    __shared__ float Bs[DIM][128];    // 32 KB
    __shared__ int   toks[CBM];
    const int tid = threadIdx.x;
    const int tx  = tid & 15;
    const int ty  = tid >> 4;
    const int cnt = g_ambcnt;

    for (int chunk = blockIdx.x; chunk * CBM < cnt; chunk += gridDim.x) {
        __syncthreads();
        if (tid < CBM) {
            int it = chunk * CBM + tid;
            toks[tid] = g_amb[it < cnt ? it : 0];
        }
        __syncthreads();
        // gather A tile transposed
        #pragma unroll
        for (int i = 0; i < 2; i++) {
            int lin = tid + i * 256;          // 512 float4
            int r = lin >> 4;
            int c = (lin & 15) << 2;
            float4 v = *reinterpret_cast<const float4*>(&x[toks[r] * DIM + c]);
            As[c + 0][r] = v.x; As[c + 1][r] = v.y; As[c + 2][r] = v.z; As[c + 3][r] = v.w;
        }

        float best[2] = {3.0e38f, 3.0e38f};
        int   bidx[2] = {0, 0};

        for (int k0 = 0; k0 < KC; k0 += 128) {
            __syncthreads();
            #pragma unroll
            for (int i = 0; i < 8; i++) {
                int lin = tid + i * 256;      // 2048 float4
                int d = lin >> 5;
                int c = (lin & 31) << 2;
                *reinterpret_cast<float4*>(&Bs[d][c]) =
                    *reinterpret_cast<const float4*>(&e[d * KC + k0 + c]);
            }
            __syncthreads();

            ull acc[2][4];
            #pragma unroll
            for (int i = 0; i < 2; i++)
                #pragma unroll
                for (int p = 0; p < 4; p++) acc[i][p] = 0ULL;

            #pragma unroll 8
            for (int d = 0; d < DIM; d++) {
                float2 av = *reinterpret_cast<const float2*>(&As[d][ty * 2]);
                ull a0 = dup2(av.x), a1 = dup2(av.y);
                ulonglong2 q0 = *reinterpret_cast<const ulonglong2*>(&Bs[d][tx * 4]);
                ulonglong2 q1 = *reinterpret_cast<const ulonglong2*>(&Bs[d][64 + tx * 4]);
                ull bp[4] = {q0.x, q0.y, q1.x, q1.y};
                #pragma unroll
                for (int p = 0; p < 4; p++) { fma2(acc[0][p], a0, bp[p]); fma2(acc[1][p], a1, bp[p]); }
            }

            #pragma unroll
            for (int p = 0; p < 4; p++) {
                int kbase = k0 + ((p < 2) ? (tx * 4 + p * 2) : (64 + tx * 4 + (p - 2) * 2));
                float2 ee = *reinterpret_cast<const float2*>(&g_ee[kbase]);
                #pragma unroll
                for (int i = 0; i < 2; i++) {
                    float2 s = unpack2(acc[i][p]);
                    float s0 = fmaf(-2.f, s.x, ee.x);
                    float s1 = fmaf(-2.f, s.y, ee.y);
                    if (s0 < best[i]) { best[i] = s0; bidx[i] = kbase; }
                    if (s1 < best[i]) { best[i] = s1; bidx[i] = kbase + 1; }
                }
            }
        }

        #pragma unroll
        for (int i = 0; i < 2; i++) {
            float v = best[i];
            int   id = bidx[i];
            #pragma unroll
            for (int off = 8; off > 0; off >>= 1) {
                float v2 = __shfl_down_sync(0xffffffffu, v, off, 16);
                int  id2 = __shfl_down_sync(0xffffffffu, id, off, 16);
                if (v2 < v || (v2 == v && id2 < id)) { v = v2; id = id2; }
            }
            if (tx == 0) g_idx[toks[ty * 2 + i]] = id;
        }
    }
}

// ---------------- gather/quantize + loss + EMA scatter ----------------
__global__ __launch_bounds__(256) void quant_kernel(const float* __restrict__ x,
                                                    float* __restrict__ out) {
    int t   = threadIdx.x;
    int tok = blockIdx.x * 4 + (t >> 6);
    int d   = t & 63;
    int idx = g_idx[tok];
    float xv = x[tok * DIM + d];
    float q  = g_eT[idx * DIM + d];
    out[tok * DIM + d] = xv + (q - xv);
    float diff = q - xv;
    float l = diff * diff;
    #pragma unroll
    for (int off = 16; off; off >>= 1) l += __shfl_down_sync(0xffffffffu, l, off);
    __shared__ float part[8];
    if ((t & 31) == 0) part[t >> 5] = l;
    if (d == 0) atomicAdd(&g_counts[idx], 1.0f);
    atomicAdd(&g_sums[idx * DIM + d], xv);
    __syncthreads();
    if (t == 0) {
        float s = 0.f;
        #pragma unroll
        for (int w = 0; w < 8; w++) s += part[w];
        g_losspart[blockIdx.x] = s;
    }
}

// ---------------- loss reduction ----------------
__global__ void loss_kernel(float* __restrict__ out) {
    int t = threadIdx.x;
    float s = 0.f;
    for (int i = t; i < NTOK / 4; i += 256) s += g_losspart[i];
    #pragma unroll
    for (int off = 16; off; off >>= 1) s += __shfl_down_sync(0xffffffffu, s, off);
    __shared__ float part[8];
    if ((t & 31) == 0) part[t >> 5] = s;
    __syncthreads();
    if (t == 0) {
        float tt = 0.f;
        #pragma unroll
        for (int w = 0; w < 8; w++) tt += part[w];
        out[OFF_LOSS] = tt * (0.25f / (float)(NTOK * DIM));
    }
}

// ---------------- new_cs + n / entropy reductions ----------------
__global__ __launch_bounds__(256) void newcs_kernel(const float* __restrict__ cs,
                                                    float* __restrict__ out) {
    int t = threadIdx.x;
    int k = blockIdx.x * 256 + t;
    float cnt = g_counts[k];
    float ncs = 0.1f * cnt + 0.9f * cs[k];
    out[OFF_NCS + k] = ncs;
    float avg = cnt * (1.0f / (float)NTOK);
    float ent = avg * logf(avg + 1e-20f);
    #pragma unroll
    for (int off = 16; off; off >>= 1) {
        ncs += __shfl_down_sync(0xffffffffu, ncs, off);
        ent += __shfl_down_sync(0xffffffffu, ent, off);
    }
    __shared__ float p1[8], p2[8];
    if ((t & 31) == 0) { p1[t >> 5] = ncs; p2[t >> 5] = ent; }
    __syncthreads();
    if (t == 0) {
        float s1 = 0.f, s2 = 0.f;
        #pragma unroll
        for (int w = 0; w < 8; w++) { s1 += p1[w]; s2 += p2[w]; }
        atomicAdd(&g_scal[0], s1);
        atomicAdd(&g_scal[1], s2);
    }
}

// ---------------- new_un, new_e, perplexity ----------------
__global__ __launch_bounds__(256) void final_kernel(const float* __restrict__ cs,
                                                    const float* __restrict__ un,
                                                    float* __restrict__ out) {
    int lin = blockIdx.x * 256 + threadIdx.x;
    int d = lin >> 12;
    int k = lin & (KC - 1);
    float nun = 0.1f * g_sums[k * DIM + d] + 0.9f * un[lin];
    out[OFF_NUN + lin] = nun;
    float n   = g_scal[0];
    float ncs = 0.1f * g_counts[k] + 0.9f * cs[k];
    float stable = (ncs + 1e-20f) / (n + 4.096e-17f) * n;
    out[OFF_NE + lin] = nun / stable;
    if (lin == 0) out[OFF_PERP] = expf(-g_scal[1]);
}

// ---------------- launch ----------------
extern "C" void kernel_launch(void* const* d_in, const int* in_sizes, int n_in,
                              void* d_out, int out_size) {
    const float* x  = (const float*)d_in[0];   // [N, D]
    const float* e  = (const float*)d_in[1];   // [D, K]
    const float* cs = (const float*)d_in[2];   // [K]
    const float* un = (const float*)d_in[3];   // [D, K]
    float* out = (float*)d_out;

    static bool attr_set = false;
    if (!attr_set) {
        cudaFuncSetAttribute(coarse_kernel, cudaFuncAttributeMaxDynamicSharedMemorySize, SMEM_DYN);
        attr_set = true;
    }

    prep_x_kernel<<<NTOK * 16 / 256, 256>>>(x);
    prep_e_kernel<<<KC / 256, 256>>>(e);
    coarse_kernel<<<NTOK / TM, 128, SMEM_DYN>>>();
    cleanup_kernel<<<128, 256>>>(x, e);
    quant_kernel<<<NTOK / 4, 256>>>(x, out);
    loss_kernel<<<1, 256>>>(out);
    newcs_kernel<<<KC / 256, 256>>>(cs, out);
    final_kernel<<<DIM * KC / 256, 256>>>(cs, un, out);
}

// round 7
// speedup vs baseline: 4.5678x; 1.5953x over previous
#include <cuda_runtime.h>
#include <cuda_fp16.h>
#include <cstdint>

#define NTOK 65536
#define DIM  64
#define KC   4096
#define NKS  4            // 64 / 16 k-steps
#define TM   128          // CTA token tile
#define TN   128          // code tile
#define NT   (KC / TN)    // 32
#define MARGIN 0.35f
#define KSPLIT 4
#define KPER (KC / KSPLIT)

// output layout: quantized_st [N*D], loss, perplexity, new_e [D*K], new_cs [K], new_un [D*K]
#define OFF_LOSS 4194304
#define OFF_PERP 4194305
#define OFF_NE   4194306
#define OFF_NCS  4456450
#define OFF_NUN  4460546

typedef unsigned long long ull;

// ---------------- device scratch ----------------
__device__ __half g_ahf[NTOK * DIM];   // 8 MB  fp16 x
__device__ __half g_bhf[KC * DIM];     // 0.5MB fp16 (-2e)
__device__ float g_eT[KC * DIM];
__device__ float g_ee[KC];
__device__ int   g_idx[NTOK];
__device__ int   g_amb[NTOK];
__device__ int   g_ambcnt;
__device__ float g_pval[NTOK * KSPLIT];
__device__ int   g_pidx[NTOK * KSPLIT];
__device__ float g_counts[KC];
__device__ float g_sums[KC * DIM];
__device__ float g_losspart[NTOK / 4];
__device__ float g_scal[2];

// ---------------- helpers ----------------
__device__ __forceinline__ uint32_t smem_u32(const void* p) {
    uint32_t a;
    asm("{ .reg .u64 t; cvta.to.shared.u64 t, %1; cvt.u32.u64 %0, t; }" : "=r"(a) : "l"(p));
    return a;
}
__device__ __forceinline__ void ldm4(uint32_t* r, uint32_t addr) {
    asm volatile("ldmatrix.sync.aligned.m8n8.x4.shared.b16 {%0,%1,%2,%3}, [%4];"
        : "=r"(r[0]), "=r"(r[1]), "=r"(r[2]), "=r"(r[3]) : "r"(addr));
}
__device__ __forceinline__ void mma_acc(float* c, const uint32_t* a, const uint32_t* b) {
    asm volatile("mma.sync.aligned.m16n8k16.row.col.f32.f16.f16.f32 "
        "{%0,%1,%2,%3}, {%4,%5,%6,%7}, {%8,%9}, {%0,%1,%2,%3};"
        : "+f"(c[0]), "+f"(c[1]), "+f"(c[2]), "+f"(c[3])
        : "r"(a[0]), "r"(a[1]), "r"(a[2]), "r"(a[3]), "r"(b[0]), "r"(b[1]));
}
__device__ __forceinline__ void mma_zero(float* c, const uint32_t* a, const uint32_t* b) {
    asm volatile("mma.sync.aligned.m16n8k16.row.col.f32.f16.f16.f32 "
        "{%0,%1,%2,%3}, {%4,%5,%6,%7}, {%8,%9}, {%10,%10,%10,%10};"
        : "=f"(c[0]), "=f"(c[1]), "=f"(c[2]), "=f"(c[3])
        : "r"(a[0]), "r"(a[1]), "r"(a[2]), "r"(a[3]), "r"(b[0]), "r"(b[1]), "f"(0.0f));
}
// f32x2 (cleanup)
__device__ __forceinline__ ull dup2(float v) {
    ull r; asm("mov.b64 %0, {%1, %1};" : "=l"(r) : "f"(v)); return r;
}
__device__ __forceinline__ void fma2(ull &acc, ull a, ull b) {
    asm("fma.rn.f32x2 %0, %1, %2, %0;" : "+l"(acc) : "l"(a), "l"(b));
}
__device__ __forceinline__ float2 unpack2(ull v) {
    float lo, hi; asm("mov.b64 {%0, %1}, %2;" : "=f"(lo), "=f"(hi) : "l"(v));
    return make_float2(lo, hi);
}

// coarse smem layout: 64 fp16/row = 128B, padded to 144B (conflict-free ldmatrix)
#define ROWB 144
#define A_OFF 0
#define B_OFF 18432
#define EE_OFF 36864
#define RED_OFF 37376
#define SMEM_DYN 39424

// ---------------- prep: x -> fp16 ----------------
__global__ void prep_x_kernel(const float* __restrict__ x) {
    int idx = blockIdx.x * 256 + threadIdx.x;   // over NTOK*16 float4
    int tok = idx >> 4;
    int d4  = (idx & 15) << 2;
    float4 v = *reinterpret_cast<const float4*>(&x[tok * DIM + d4]);
    __half2* hp = reinterpret_cast<__half2*>(&g_ahf[tok * DIM + d4]);
    hp[0] = __floats2half2_rn(v.x, v.y);
    hp[1] = __floats2half2_rn(v.z, v.w);
}

// ---------------- prep: e -> eT, ee, fp16(-2e), zero scratch ----------
__global__ void prep_e_kernel(const float* __restrict__ e) {
    int k = blockIdx.x * blockDim.x + threadIdx.x;
    float s = 0.f;
    __half* row = &g_bhf[k * DIM];
    #pragma unroll 8
    for (int d = 0; d < DIM; d++) {
        float v = e[d * KC + k];
        g_eT[k * DIM + d] = v;
        g_sums[k * DIM + d] = 0.f;
        s = fmaf(v, v, s);
        row[d] = __float2half_rn(-2.f * v);
    }
    g_ee[k] = s;
    g_counts[k] = 0.f;
    if (k < 2) g_scal[k] = 0.f;
    if (k == 0) g_ambcnt = 0;
}

// ---------------- coarse: fp16 mma.sync distance GEMM + packed argmin ----------
// 128 threads = 4 warps (2x2). Warp tile 64x64, mma m16n8k16, mf=4, nf=8, K=64.
__global__ void __launch_bounds__(128) coarse_kernel() {
    extern __shared__ __align__(16) char sm[];
    const uint32_t sb = smem_u32(sm);
    const int tid  = threadIdx.x;
    const int wid  = tid >> 5;
    const int lane = tid & 31;
    const int wm   = wid >> 1;
    const int wn   = wid & 1;
    const int m0   = blockIdx.x * TM;
    float* ee_s = reinterpret_cast<float*>(sm + EE_OFF);
    int*   red  = reinterpret_cast<int*>(sm + RED_OFF);

    // A tile load: 128 rows x 64 fp16 (8 uint4 per row)
    #pragma unroll
    for (int i = 0; i < 8; i++) {
        int lin = tid + i * 128;            // 1024 uint4
        int row = lin >> 3;
        int c16 = lin & 7;
        uint4 v = *reinterpret_cast<const uint4*>(&g_ahf[(m0 + row) * DIM + c16 * 8]);
        *reinterpret_cast<uint4*>(sm + A_OFF + row * ROWB + c16 * 16) = v;
    }

    const uint32_t a_base = sb + A_OFF + (wm * 64 + (lane & 15)) * ROWB + (lane & 16);
    const uint32_t b_base = sb + B_OFF + (wn * 64 + ((lane & 7) + ((lane & 16) >> 1))) * ROWB
                            + ((lane & 8) << 1);

    int pk1[8], pk2[8];
    #pragma unroll
    for (int r = 0; r < 8; r++) { pk1[r] = 0x7FFFFFFF; pk2[r] = 0x7FFFFFFF; }

    const int cbl = wn * 64 + (lane & 3) * 2;

    #pragma unroll 1
    for (int nt = 0; nt < NT; nt++) {
        __syncthreads();
        #pragma unroll
        for (int i = 0; i < 8; i++) {
            int lin = tid + i * 128;
            int row = lin >> 3;
            int c16 = lin & 7;
            uint4 v = *reinterpret_cast<const uint4*>(&g_bhf[(nt * TN + row) * DIM + c16 * 8]);
            *reinterpret_cast<uint4*>(sm + B_OFF + row * ROWB + c16 * 16) = v;
        }
        ee_s[tid] = g_ee[nt * TN + tid];
        __syncthreads();

        float acc[4][8][4];
        #pragma unroll
        for (int ks = 0; ks < NKS; ks++) {
            uint32_t af[4][4], bq[4][4];
            #pragma unroll
            for (int mf = 0; mf < 4; mf++) ldm4(af[mf], a_base + mf * (16 * ROWB) + ks * 32);
            #pragma unroll
            for (int q = 0; q < 4; q++)    ldm4(bq[q], b_base + q * (16 * ROWB) + ks * 32);
            #pragma unroll
            for (int mf = 0; mf < 4; mf++)
                #pragma unroll
                for (int nf = 0; nf < 8; nf++) {
                    const uint32_t* b = &bq[nf >> 1][(nf & 1) * 2];
                    if (ks == 0) mma_zero(acc[mf][nf], af[mf], b);
                    else         mma_acc(acc[mf][nf], af[mf], b);
                }
        }

        // epilogue: packed (score|idx) min + second-min
        const int kb = nt * TN + cbl;
        #pragma unroll
        for (int nf = 0; nf < 8; nf++) {
            float ee0 = ee_s[cbl + nf * 8];
            float ee1 = ee_s[cbl + nf * 8 + 1];
            int k0 = kb + nf * 8, k1 = k0 + 1;
            #pragma unroll
            for (int mf = 0; mf < 4; mf++) {
                #pragma unroll
                for (int h = 0; h < 2; h++) {
                    int r = 2 * mf + h;
                    float v0 = acc[mf][nf][2 * h + 0] + ee0;
                    float v1 = acc[mf][nf][2 * h + 1] + ee1;
                    int p0 = (__float_as_int(v0) & 0xFFFFF000) | k0;
                    int t0 = max(pk1[r], p0);
                    pk1[r] = min(pk1[r], p0);
                    pk2[r] = min(pk2[r], t0);
                    int p1 = (__float_as_int(v1) & 0xFFFFF000) | k1;
                    int t1 = max(pk1[r], p1);
                    pk1[r] = min(pk1[r], p1);
                    pk2[r] = min(pk2[r], t1);
                }
            }
        }
    }

    #pragma unroll
    for (int r = 0; r < 8; r++) {
        #pragma unroll
        for (int m = 1; m <= 2; m <<= 1) {
            int q1 = __shfl_xor_sync(0xffffffffu, pk1[r], m);
            int q2 = __shfl_xor_sync(0xffffffffu, pk2[r], m);
            int t  = max(pk1[r], q1);
            pk1[r] = min(pk1[r], q1);
            pk2[r] = min(min(pk2[r], q2), t);
        }
    }
    __syncthreads();
    if ((lane & 3) == 0) {
        #pragma unroll
        for (int r = 0; r < 8; r++) {
            int row = wm * 64 + (r >> 1) * 16 + (lane >> 2) + (r & 1) * 8;
            red[row * 4 + wn * 2 + 0] = pk1[r];
            red[row * 4 + wn * 2 + 1] = pk2[r];
        }
    }
    __syncthreads();
    {
        int row = tid;
        int p1a = red[row * 4 + 0], p2a = red[row * 4 + 1];
        int p1b = red[row * 4 + 2], p2b = red[row * 4 + 3];
        int t  = max(p1a, p1b);
        int p1 = min(p1a, p1b);
        int p2 = min(min(p2a, p2b), t);
        int tok = m0 + row;
        g_idx[tok] = p1 & 0xFFF;
        float f1 = __int_as_float(p1 & 0xFFFFF000);
        float f2 = __int_as_float(p2 & 0xFFFFF000);
        // NOTE: packed-int ordering is inverted for negative floats, but any token
        // with >=2 negative scores then yields f2 - f1 <= 0 < MARGIN -> rescanned.
        if (f2 - f1 < MARGIN) {
            int pos = atomicAdd(&g_ambcnt, 1);
            g_amb[pos] = tok;
        }
    }
}

// ---------------- cleanup: exact fp32 (f32x2) split-K rescan of ambiguous --------
#define CBM 32
__global__ __launch_bounds__(256) void cleanup_kernel(const float* __restrict__ x,
                                                      const float* __restrict__ e) {
    __shared__ float As[DIM][CBM];
    __shared__ float Bs[DIM][128];
    __shared__ int   toks[CBM];
    const int tid = threadIdx.x;
    const int tx  = tid & 15;
    const int ty  = tid >> 4;
    const int spl = blockIdx.y;
    const int kbeg = spl * KPER;
    const int cnt = g_ambcnt;

    for (int chunk = blockIdx.x; chunk * CBM < cnt; chunk += gridDim.x) {
        __syncthreads();
        if (tid < CBM) {
            int it = chunk * CBM + tid;
            toks[tid] = g_amb[it < cnt ? it : 0];
        }
        __syncthreads();
        #pragma unroll
        for (int i = 0; i < 2; i++) {
            int lin = tid + i * 256;
            int r = lin >> 4;
            int c = (lin & 15) << 2;
            float4 v = *reinterpret_cast<const float4*>(&x[toks[r] * DIM + c]);
            As[c + 0][r] = v.x; As[c + 1][r] = v.y; As[c + 2][r] = v.z; As[c + 3][r] = v.w;
        }

        float best[2] = {3.0e38f, 3.0e38f};
        int   bidx[2] = {0, 0};

        for (int k0 = kbeg; k0 < kbeg + KPER; k0 += 128) {
            __syncthreads();
            #pragma unroll
            for (int i = 0; i < 8; i++) {
                int lin = tid + i * 256;
                int d = lin >> 5;
                int c = (lin & 31) << 2;
                *reinterpret_cast<float4*>(&Bs[d][c]) =
                    *reinterpret_cast<const float4*>(&e[d * KC + k0 + c]);
            }
            __syncthreads();

            ull acc[2][4];
            #pragma unroll
            for (int i = 0; i < 2; i++)
                #pragma unroll
                for (int p = 0; p < 4; p++) acc[i][p] = 0ULL;

            #pragma unroll 8
            for (int d = 0; d < DIM; d++) {
                float2 av = *reinterpret_cast<const float2*>(&As[d][ty * 2]);
                ull a0 = dup2(av.x), a1 = dup2(av.y);
                ulonglong2 q0 = *reinterpret_cast<const ulonglong2*>(&Bs[d][tx * 4]);
                ulonglong2 q1 = *reinterpret_cast<const ulonglong2*>(&Bs[d][64 + tx * 4]);
                ull bp[4] = {q0.x, q0.y, q1.x, q1.y};
                #pragma unroll
                for (int p = 0; p < 4; p++) { fma2(acc[0][p], a0, bp[p]); fma2(acc[1][p], a1, bp[p]); }
            }

            #pragma unroll
            for (int p = 0; p < 4; p++) {
                int kbase = k0 + ((p < 2) ? (tx * 4 + p * 2) : (64 + tx * 4 + (p - 2) * 2));
                float2 ee = *reinterpret_cast<const float2*>(&g_ee[kbase]);
                #pragma unroll
                for (int i = 0; i < 2; i++) {
                    float2 s = unpack2(acc[i][p]);
                    float s0 = fmaf(-2.f, s.x, ee.x);
                    float s1 = fmaf(-2.f, s.y, ee.y);
                    if (s0 < best[i]) { best[i] = s0; bidx[i] = kbase; }
                    if (s1 < best[i]) { best[i] = s1; bidx[i] = kbase + 1; }
                }
            }
        }

        #pragma unroll
        for (int i = 0; i < 2; i++) {
            float v = best[i];
            int   id = bidx[i];
            #pragma unroll
            for (int off = 8; off > 0; off >>= 1) {
                float v2 = __shfl_down_sync(0xffffffffu, v, off, 16);
                int  id2 = __shfl_down_sync(0xffffffffu, id, off, 16);
                if (v2 < v || (v2 == v && id2 < id)) { v = v2; id = id2; }
            }
            if (tx == 0) {
                int tok = toks[ty * 2 + i];
                g_pval[tok * KSPLIT + spl] = v;
                g_pidx[tok * KSPLIT + spl] = id;
            }
        }
    }
}

// ---------------- combine split-K partials for ambiguous tokens ----------------
__global__ void combine_kernel() {
    int cnt = g_ambcnt;
    for (int i = blockIdx.x * 256 + threadIdx.x; i < cnt; i += gridDim.x * 256) {
        int tok = g_amb[i];
        float v = g_pval[tok * KSPLIT];
        int  id = g_pidx[tok * KSPLIT];
        #pragma unroll
        for (int s = 1; s < KSPLIT; s++) {
            float v2 = g_pval[tok * KSPLIT + s];
            int  id2 = g_pidx[tok * KSPLIT + s];
            if (v2 < v) { v = v2; id = id2; }
        }
        g_idx[tok] = id;
    }
}

// ---------------- gather/quantize + loss + EMA scatter ----------------
__global__ __launch_bounds__(256) void quant_kernel(const float* __restrict__ x,
                                                    float* __restrict__ out) {
    int t   = threadIdx.x;
    int tok = blockIdx.x * 4 + (t >> 6);
    int d   = t & 63;
    int idx = g_idx[tok];
    float xv = x[tok * DIM + d];
    float q  = g_eT[idx * DIM + d];
    out[tok * DIM + d] = xv + (q - xv);
    float diff = q - xv;
    float l = diff * diff;
    #pragma unroll
    for (int off = 16; off; off >>= 1) l += __shfl_down_sync(0xffffffffu, l, off);
    __shared__ float part[8];
    if ((t & 31) == 0) part[t >> 5] = l;
    if (d == 0) atomicAdd(&g_counts[idx], 1.0f);
    atomicAdd(&g_sums[idx * DIM + d], xv);
    __syncthreads();
    if (t == 0) {
        float s = 0.f;
        #pragma unroll
        for (int w = 0; w < 8; w++) s += part[w];
        g_losspart[blockIdx.x] = s;
    }
}

// ---------------- loss reduction ----------------
__global__ void loss_kernel(float* __restrict__ out) {
    int t = threadIdx.x;
    float s = 0.f;
    for (int i = t; i < NTOK / 4; i += 256) s += g_losspart[i];
    #pragma unroll
    for (int off = 16; off; off >>= 1) s += __shfl_down_sync(0xffffffffu, s, off);
    __shared__ float part[8];
    if ((t & 31) == 0) part[t >> 5] = s;
    __syncthreads();
    if (t == 0) {
        float tt = 0.f;
        #pragma unroll
        for (int w = 0; w < 8; w++) tt += part[w];
        out[OFF_LOSS] = tt * (0.25f / (float)(NTOK * DIM));
    }
}

// ---------------- new_cs + n / entropy reductions ----------------
__global__ __launch_bounds__(256) void newcs_kernel(const float* __restrict__ cs,
                                                    float* __restrict__ out) {
    int t = threadIdx.x;
    int k = blockIdx.x * 256 + t;
    float cnt = g_counts[k];
    float ncs = 0.1f * cnt + 0.9f * cs[k];
    out[OFF_NCS + k] = ncs;
    float avg = cnt * (1.0f / (float)NTOK);
    float ent = avg * logf(avg + 1e-20f);
    #pragma unroll
    for (int off = 16; off; off >>= 1) {
        ncs += __shfl_down_sync(0xffffffffu, ncs, off);
        ent += __shfl_down_sync(0xffffffffu, ent, off);
    }
    __shared__ float p1[8], p2[8];
    if ((t & 31) == 0) { p1[t >> 5] = ncs; p2[t >> 5] = ent; }
    __syncthreads();
    if (t == 0) {
        float s1 = 0.f, s2 = 0.f;
        #pragma unroll
        for (int w = 0; w < 8; w++) { s1 += p1[w]; s2 += p2[w]; }
        atomicAdd(&g_scal[0], s1);
        atomicAdd(&g_scal[1], s2);
    }
}

// ---------------- new_un, new_e, perplexity ----------------
__global__ __launch_bounds__(256) void final_kernel(const float* __restrict__ cs,
                                                    const float* __restrict__ un,
                                                    float* __restrict__ out) {
    int lin = blockIdx.x * 256 + threadIdx.x;
    int d = lin >> 12;
    int k = lin & (KC - 1);
    float nun = 0.1f * g_sums[k * DIM + d] + 0.9f * un[lin];
    out[OFF_NUN + lin] = nun;
    float n   = g_scal[0];
    float ncs = 0.1f * g_counts[k] + 0.9f * cs[k];
    float stable = (ncs + 1e-20f) / (n + 4.096e-17f) * n;
    out[OFF_NE + lin] = nun / stable;
    if (lin == 0) out[OFF_PERP] = expf(-g_scal[1]);
}

// ---------------- launch ----------------
extern "C" void kernel_launch(void* const* d_in, const int* in_sizes, int n_in,
                              void* d_out, int out_size) {
    const float* x  = (const float*)d_in[0];   // [N, D]
    const float* e  = (const float*)d_in[1];   // [D, K]
    const float* cs = (const float*)d_in[2];   // [K]
    const float* un = (const float*)d_in[3];   // [D, K]
    float* out = (float*)d_out;

    prep_x_kernel<<<NTOK * 16 / 256, 256>>>(x);
    prep_e_kernel<<<KC / 256, 256>>>(e);
    coarse_kernel<<<NTOK / TM, 128, SMEM_DYN>>>();
    cleanup_kernel<<<dim3(192, KSPLIT), 256>>>(x, e);
    combine_kernel<<<64, 256>>>();
    quant_kernel<<<NTOK / 4, 256>>>(x, out);
    loss_kernel<<<1, 256>>>(out);
    newcs_kernel<<<KC / 256, 256>>>(cs, out);
    final_kernel<<<DIM * KC / 256, 256>>>(cs, un, out);
}

// round 8
// speedup vs baseline: 5.9186x; 1.2957x over previous
#include <cuda_runtime.h>
#include <cuda_fp16.h>
#include <cstdint>

#define NTOK 65536
#define DIM  64
#define KC   4096
#define NKS  4            // 64 / 16 k-steps
#define TM   128          // CTA token tile
#define TN   128          // code tile
#define NT   (KC / TN)    // 32
#define MARGIN 0.35f
#define KSPLIT 4
#define KPER (KC / KSPLIT)

// output layout: quantized_st [N*D], loss, perplexity, new_e [D*K], new_cs [K], new_un [D*K]
#define OFF_LOSS 4194304
#define OFF_PERP 4194305
#define OFF_NE   4194306
#define OFF_NCS  4456450
#define OFF_NUN  4460546

typedef unsigned long long ull;

// ---------------- device scratch ----------------
__device__ __half g_ahf[NTOK * DIM];   // 8 MB  fp16 x
__device__ __half g_bhf[KC * DIM];     // 0.5MB fp16 (-2e)
__device__ float g_xx[NTOK];           // ||x||^2 per token
__device__ float g_eT[KC * DIM];
__device__ float g_ee[KC];
__device__ int   g_idx[NTOK];
__device__ int   g_amb[NTOK];
__device__ int   g_ambcnt;
__device__ float g_pval[NTOK * KSPLIT];
__device__ int   g_pidx[NTOK * KSPLIT];
__device__ float g_counts[KC];
__device__ float g_sums[KC * DIM];
__device__ float g_losspart[NTOK / 4];
__device__ float g_scal[2];

// ---------------- helpers ----------------
__device__ __forceinline__ uint32_t smem_u32(const void* p) {
    uint32_t a;
    asm("{ .reg .u64 t; cvta.to.shared.u64 t, %1; cvt.u32.u64 %0, t; }" : "=r"(a) : "l"(p));
    return a;
}
__device__ __forceinline__ void ldm4(uint32_t* r, uint32_t addr) {
    asm volatile("ldmatrix.sync.aligned.m8n8.x4.shared.b16 {%0,%1,%2,%3}, [%4];"
        : "=r"(r[0]), "=r"(r[1]), "=r"(r[2]), "=r"(r[3]) : "r"(addr));
}
__device__ __forceinline__ void mma_acc(float* c, const uint32_t* a, const uint32_t* b) {
    asm volatile("mma.sync.aligned.m16n8k16.row.col.f32.f16.f16.f32 "
        "{%0,%1,%2,%3}, {%4,%5,%6,%7}, {%8,%9}, {%0,%1,%2,%3};"
        : "+f"(c[0]), "+f"(c[1]), "+f"(c[2]), "+f"(c[3])
        : "r"(a[0]), "r"(a[1]), "r"(a[2]), "r"(a[3]), "r"(b[0]), "r"(b[1]));
}
__device__ __forceinline__ void mma_zero(float* c, const uint32_t* a, const uint32_t* b) {
    asm volatile("mma.sync.aligned.m16n8k16.row.col.f32.f16.f16.f32 "
        "{%0,%1,%2,%3}, {%4,%5,%6,%7}, {%8,%9}, {%10,%10,%10,%10};"
        : "=f"(c[0]), "=f"(c[1]), "=f"(c[2]), "=f"(c[3])
        : "r"(a[0]), "r"(a[1]), "r"(a[2]), "r"(a[3]), "r"(b[0]), "r"(b[1]), "f"(0.0f));
}
// f32x2 (cleanup)
__device__ __forceinline__ ull dup2(float v) {
    ull r; asm("mov.b64 %0, {%1, %1};" : "=l"(r) : "f"(v)); return r;
}
__device__ __forceinline__ void fma2(ull &acc, ull a, ull b) {
    asm("fma.rn.f32x2 %0, %1, %2, %0;" : "+l"(acc) : "l"(a), "l"(b));
}
__device__ __forceinline__ float2 unpack2(ull v) {
    float lo, hi; asm("mov.b64 {%0, %1}, %2;" : "=f"(lo), "=f"(hi) : "l"(v));
    return make_float2(lo, hi);
}

// coarse smem layout: 64 fp16/row = 128B, padded to 144B (conflict-free ldmatrix)
#define ROWB 144
#define A_OFF 0
#define B_OFF 18432
#define EE_OFF 36864
#define RED_OFF 37376
#define XX_OFF 39424
#define SMEM_DYN 39936

// ---------------- prep: x -> fp16, ||x||^2 ----------------
__global__ void prep_x_kernel(const float* __restrict__ x) {
    int idx = blockIdx.x * 256 + threadIdx.x;   // over NTOK*16 float4
    int tok = idx >> 4;
    int d4  = (idx & 15) << 2;
    float4 v = *reinterpret_cast<const float4*>(&x[tok * DIM + d4]);
    __half2* hp = reinterpret_cast<__half2*>(&g_ahf[tok * DIM + d4]);
    hp[0] = __floats2half2_rn(v.x, v.y);
    hp[1] = __floats2half2_rn(v.z, v.w);
    float s = v.x * v.x + v.y * v.y + v.z * v.z + v.w * v.w;
    #pragma unroll
    for (int off = 8; off; off >>= 1) s += __shfl_xor_sync(0xffffffffu, s, off, 16);
    if ((idx & 15) == 0) g_xx[tok] = s;
}

// ---------------- prep: e -> eT, ee, fp16(-2e), zero scratch ----------
__global__ void prep_e_kernel(const float* __restrict__ e) {
    int k = blockIdx.x * blockDim.x + threadIdx.x;
    float s = 0.f;
    __half* row = &g_bhf[k * DIM];
    #pragma unroll 8
    for (int d = 0; d < DIM; d++) {
        float v = e[d * KC + k];
        g_eT[k * DIM + d] = v;
        g_sums[k * DIM + d] = 0.f;
        s = fmaf(v, v, s);
        row[d] = __float2half_rn(-2.f * v);
    }
    g_ee[k] = s;
    g_counts[k] = 0.f;
    if (k < 2) g_scal[k] = 0.f;
    if (k == 0) g_ambcnt = 0;
}

// ---------------- coarse: fp16 mma.sync distance GEMM + packed argmin ----------
// 128 threads = 4 warps (2x2). Warp tile 64x64, mma m16n8k16, mf=4, nf=8, K=64.
// score = ||x||^2 + ||e||^2 - 2 x.e >= 0  -> packed-int min ordering exact.
__global__ void __launch_bounds__(128) coarse_kernel() {
    extern __shared__ __align__(16) char sm[];
    const uint32_t sb = smem_u32(sm);
    const int tid  = threadIdx.x;
    const int wid  = tid >> 5;
    const int lane = tid & 31;
    const int wm   = wid >> 1;
    const int wn   = wid & 1;
    const int m0   = blockIdx.x * TM;
    float* ee_s = reinterpret_cast<float*>(sm + EE_OFF);
    int*   red  = reinterpret_cast<int*>(sm + RED_OFF);
    float* xx_s = reinterpret_cast<float*>(sm + XX_OFF);

    // A tile load: 128 rows x 64 fp16 (8 uint4 per row) + xx
    #pragma unroll
    for (int i = 0; i < 8; i++) {
        int lin = tid + i * 128;            // 1024 uint4
        int row = lin >> 3;
        int c16 = lin & 7;
        uint4 v = *reinterpret_cast<const uint4*>(&g_ahf[(m0 + row) * DIM + c16 * 8]);
        *reinterpret_cast<uint4*>(sm + A_OFF + row * ROWB + c16 * 16) = v;
    }
    xx_s[tid] = g_xx[m0 + tid];
    __syncthreads();

    // per-row ||x||^2 for this thread's 8 accumulator rows
    float xr[8];
    #pragma unroll
    for (int mf = 0; mf < 4; mf++)
        #pragma unroll
        for (int h = 0; h < 2; h++)
            xr[2 * mf + h] = xx_s[wm * 64 + mf * 16 + (lane >> 2) + h * 8];

    const uint32_t a_base = sb + A_OFF + (wm * 64 + (lane & 15)) * ROWB + (lane & 16);
    const uint32_t b_base = sb + B_OFF + (wn * 64 + ((lane & 7) + ((lane & 16) >> 1))) * ROWB
                            + ((lane & 8) << 1);

    int pk1[8], pk2[8];
    #pragma unroll
    for (int r = 0; r < 8; r++) { pk1[r] = 0x7FFFFFFF; pk2[r] = 0x7FFFFFFF; }

    const int cbl = wn * 64 + (lane & 3) * 2;

    #pragma unroll 1
    for (int nt = 0; nt < NT; nt++) {
        __syncthreads();
        #pragma unroll
        for (int i = 0; i < 8; i++) {
            int lin = tid + i * 128;
            int row = lin >> 3;
            int c16 = lin & 7;
            uint4 v = *reinterpret_cast<const uint4*>(&g_bhf[(nt * TN + row) * DIM + c16 * 8]);
            *reinterpret_cast<uint4*>(sm + B_OFF + row * ROWB + c16 * 16) = v;
        }
        ee_s[tid] = g_ee[nt * TN + tid];
        __syncthreads();

        float acc[4][8][4];
        #pragma unroll
        for (int ks = 0; ks < NKS; ks++) {
            uint32_t af[4][4], bq[4][4];
            #pragma unroll
            for (int mf = 0; mf < 4; mf++) ldm4(af[mf], a_base + mf * (16 * ROWB) + ks * 32);
            #pragma unroll
            for (int q = 0; q < 4; q++)    ldm4(bq[q], b_base + q * (16 * ROWB) + ks * 32);
            #pragma unroll
            for (int mf = 0; mf < 4; mf++)
                #pragma unroll
                for (int nf = 0; nf < 8; nf++) {
                    const uint32_t* b = &bq[nf >> 1][(nf & 1) * 2];
                    if (ks == 0) mma_zero(acc[mf][nf], af[mf], b);
                    else         mma_acc(acc[mf][nf], af[mf], b);
                }
        }

        // epilogue: packed (dist|idx) min + second-min; dist >= 0
        const int kb = nt * TN + cbl;
        #pragma unroll
        for (int nf = 0; nf < 8; nf++) {
            float ee0 = ee_s[cbl + nf * 8];
            float ee1 = ee_s[cbl + nf * 8 + 1];
            int k0 = kb + nf * 8, k1 = k0 + 1;
            #pragma unroll
            for (int mf = 0; mf < 4; mf++) {
                #pragma unroll
                for (int h = 0; h < 2; h++) {
                    int r = 2 * mf + h;
                    float v0 = acc[mf][nf][2 * h + 0] + ee0 + xr[r];
                    float v1 = acc[mf][nf][2 * h + 1] + ee1 + xr[r];
                    int p0 = (__float_as_int(v0) & 0xFFFFF000) | k0;
                    int t0 = max(pk1[r], p0);
                    pk1[r] = min(pk1[r], p0);
                    pk2[r] = min(pk2[r], t0);
                    int p1 = (__float_as_int(v1) & 0xFFFFF000) | k1;
                    int t1 = max(pk1[r], p1);
                    pk1[r] = min(pk1[r], p1);
                    pk2[r] = min(pk2[r], t1);
                }
            }
        }
    }

    #pragma unroll
    for (int r = 0; r < 8; r++) {
        #pragma unroll
        for (int m = 1; m <= 2; m <<= 1) {
            int q1 = __shfl_xor_sync(0xffffffffu, pk1[r], m);
            int q2 = __shfl_xor_sync(0xffffffffu, pk2[r], m);
            int t  = max(pk1[r], q1);
            pk1[r] = min(pk1[r], q1);
            pk2[r] = min(min(pk2[r], q2), t);
        }
    }
    __syncthreads();
    if ((lane & 3) == 0) {
        #pragma unroll
        for (int r = 0; r < 8; r++) {
            int row = wm * 64 + (r >> 1) * 16 + (lane >> 2) + (r & 1) * 8;
            red[row * 4 + wn * 2 + 0] = pk1[r];
            red[row * 4 + wn * 2 + 1] = pk2[r];
        }
    }
    __syncthreads();
    {
        int row = tid;
        int p1a = red[row * 4 + 0], p2a = red[row * 4 + 1];
        int p1b = red[row * 4 + 2], p2b = red[row * 4 + 3];
        int t  = max(p1a, p1b);
        int p1 = min(p1a, p1b);
        int p2 = min(min(p2a, p2b), t);
        int tok = m0 + row;
        g_idx[tok] = p1 & 0xFFF;
        float f1 = __int_as_float(p1 & 0xFFFFF000);
        float f2 = __int_as_float(p2 & 0xFFFFF000);
        if (f2 - f1 < MARGIN) {
            int pos = atomicAdd(&g_ambcnt, 1);
            g_amb[pos] = tok;
        }
    }
}

// ---------------- cleanup: exact fp32 (f32x2) split-K rescan of ambiguous --------
#define CBM 32
__global__ __launch_bounds__(256) void cleanup_kernel(const float* __restrict__ x,
                                                      const float* __restrict__ e) {
    __shared__ float As[DIM][CBM];
    __shared__ float Bs[DIM][128];
    __shared__ int   toks[CBM];
    const int tid = threadIdx.x;
    const int tx  = tid & 15;
    const int ty  = tid >> 4;
    const int spl = blockIdx.y;
    const int kbeg = spl * KPER;
    const int cnt = g_ambcnt;

    for (int chunk = blockIdx.x; chunk * CBM < cnt; chunk += gridDim.x) {
        __syncthreads();
        if (tid < CBM) {
            int it = chunk * CBM + tid;
            toks[tid] = g_amb[it < cnt ? it : 0];
        }
        __syncthreads();
        #pragma unroll
        for (int i = 0; i < 2; i++) {
            int lin = tid + i * 256;
            int r = lin >> 4;
            int c = (lin & 15) << 2;
            float4 v = *reinterpret_cast<const float4*>(&x[toks[r] * DIM + c]);
            As[c + 0][r] = v.x; As[c + 1][r] = v.y; As[c + 2][r] = v.z; As[c + 3][r] = v.w;
        }

        float best[2] = {3.0e38f, 3.0e38f};
        int   bidx[2] = {0, 0};

        for (int k0 = kbeg; k0 < kbeg + KPER; k0 += 128) {
            __syncthreads();
            #pragma unroll
            for (int i = 0; i < 8; i++) {
                int lin = tid + i * 256;
                int d = lin >> 5;
                int c = (lin & 31) << 2;
                *reinterpret_cast<float4*>(&Bs[d][c]) =
                    *reinterpret_cast<const float4*>(&e[d * KC + k0 + c]);
            }
            __syncthreads();

            ull acc[2][4];
            #pragma unroll
            for (int i = 0; i < 2; i++)
                #pragma unroll
                for (int p = 0; p < 4; p++) acc[i][p] = 0ULL;

            #pragma unroll 8
            for (int d = 0; d < DIM; d++) {
                float2 av = *reinterpret_cast<const float2*>(&As[d][ty * 2]);
                ull a0 = dup2(av.x), a1 = dup2(av.y);
                ulonglong2 q0 = *reinterpret_cast<const ulonglong2*>(&Bs[d][tx * 4]);
                ulonglong2 q1 = *reinterpret_cast<const ulonglong2*>(&Bs[d][64 + tx * 4]);
                ull bp[4] = {q0.x, q0.y, q1.x, q1.y};
                #pragma unroll
                for (int p = 0; p < 4; p++) { fma2(acc[0][p], a0, bp[p]); fma2(acc[1][p], a1, bp[p]); }
            }

            #pragma unroll
            for (int p = 0; p < 4; p++) {
                int kbase = k0 + ((p < 2) ? (tx * 4 + p * 2) : (64 + tx * 4 + (p - 2) * 2));
                float2 ee = *reinterpret_cast<const float2*>(&g_ee[kbase]);
                #pragma unroll
                for (int i = 0; i < 2; i++) {
                    float2 s = unpack2(acc[i][p]);
                    float s0 = fmaf(-2.f, s.x, ee.x);
                    float s1 = fmaf(-2.f, s.y, ee.y);
                    if (s0 < best[i]) { best[i] = s0; bidx[i] = kbase; }
                    if (s1 < best[i]) { best[i] = s1; bidx[i] = kbase + 1; }
                }
            }
        }

        #pragma unroll
        for (int i = 0; i < 2; i++) {
            float v = best[i];
            int   id = bidx[i];
            #pragma unroll
            for (int off = 8; off > 0; off >>= 1) {
                float v2 = __shfl_down_sync(0xffffffffu, v, off, 16);
                int  id2 = __shfl_down_sync(0xffffffffu, id, off, 16);
                if (v2 < v || (v2 == v && id2 < id)) { v = v2; id = id2; }
            }
            if (tx == 0) {
                int tok = toks[ty * 2 + i];
                g_pval[tok * KSPLIT + spl] = v;
                g_pidx[tok * KSPLIT + spl] = id;
            }
        }
    }
}

// ---------------- combine split-K partials for ambiguous tokens ----------------
__global__ void combine_kernel() {
    int cnt = g_ambcnt;
    for (int i = blockIdx.x * 256 + threadIdx.x; i < cnt; i += gridDim.x * 256) {
        int tok = g_amb[i];
        float v = g_pval[tok * KSPLIT];
        int  id = g_pidx[tok * KSPLIT];
        #pragma unroll
        for (int s = 1; s < KSPLIT; s++) {
            float v2 = g_pval[tok * KSPLIT + s];
            int  id2 = g_pidx[tok * KSPLIT + s];
            if (v2 < v) { v = v2; id = id2; }
        }
        g_idx[tok] = id;
    }
}

// ---------------- gather/quantize + loss + EMA scatter ----------------
__global__ __launch_bounds__(256) void quant_kernel(const float* __restrict__ x,
                                                    float* __restrict__ out) {
    int t   = threadIdx.x;
    int tok = blockIdx.x * 4 + (t >> 6);
    int d   = t & 63;
    int idx = g_idx[tok];
    float xv = x[tok * DIM + d];
    float q  = g_eT[idx * DIM + d];
    out[tok * DIM + d] = xv + (q - xv);
    float diff = q - xv;
    float l = diff * diff;
    #pragma unroll
    for (int off = 16; off; off >>= 1) l += __shfl_down_sync(0xffffffffu, l, off);
    __shared__ float part[8];
    if ((t & 31) == 0) part[t >> 5] = l;
    if (d == 0) atomicAdd(&g_counts[idx], 1.0f);
    atomicAdd(&g_sums[idx * DIM + d], xv);
    __syncthreads();
    if (t == 0) {
        float s = 0.f;
        #pragma unroll
        for (int w = 0; w < 8; w++) s += part[w];
        g_losspart[blockIdx.x] = s;
    }
}

// ---------------- loss reduction ----------------
__global__ void loss_kernel(float* __restrict__ out) {
    int t = threadIdx.x;
    float s = 0.f;
    for (int i = t; i < NTOK / 4; i += 256) s += g_losspart[i];
    #pragma unroll
    for (int off = 16; off; off >>= 1) s += __shfl_down_sync(0xffffffffu, s, off);
    __shared__ float part[8];
    if ((t & 31) == 0) part[t >> 5] = s;
    __syncthreads();
    if (t == 0) {
        float tt = 0.f;
        #pragma unroll
        for (int w = 0; w < 8; w++) tt += part[w];
        out[OFF_LOSS] = tt * (0.25f / (float)(NTOK * DIM));
    }
}

// ---------------- new_cs + n / entropy reductions ----------------
__global__ __launch_bounds__(256) void newcs_kernel(const float* __restrict__ cs,
                                                    float* __restrict__ out) {
    int t = threadIdx.x;
    int k = blockIdx.x * 256 + t;
    float cnt = g_counts[k];
    float ncs = 0.1f * cnt + 0.9f * cs[k];
    out[OFF_NCS + k] = ncs;
    float avg = cnt * (1.0f / (float)NTOK);
    float ent = avg * logf(avg + 1e-20f);
    #pragma unroll
    for (int off = 16; off; off >>= 1) {
        ncs += __shfl_down_sync(0xffffffffu, ncs, off);
        ent += __shfl_down_sync(0xffffffffu, ent, off);
    }
    __shared__ float p1[8], p2[8];
    if ((t & 31) == 0) { p1[t >> 5] = ncs; p2[t >> 5] = ent; }
    __syncthreads();
    if (t == 0) {
        float s1 = 0.f, s2 = 0.f;
        #pragma unroll
        for (int w = 0; w < 8; w++) { s1 += p1[w]; s2 += p2[w]; }
        atomicAdd(&g_scal[0], s1);
        atomicAdd(&g_scal[1], s2);
    }
}

// ---------------- new_un, new_e, perplexity ----------------
__global__ __launch_bounds__(256) void final_kernel(const float* __restrict__ cs,
                                                    const float* __restrict__ un,
                                                    float* __restrict__ out) {
    int lin = blockIdx.x * 256 + threadIdx.x;
    int d = lin >> 12;
    int k = lin & (KC - 1);
    float nun = 0.1f * g_sums[k * DIM + d] + 0.9f * un[lin];
    out[OFF_NUN + lin] = nun;
    float n   = g_scal[0];
    float ncs = 0.1f * g_counts[k] + 0.9f * cs[k];
    float stable = (ncs + 1e-20f) / (n + 4.096e-17f) * n;
    out[OFF_NE + lin] = nun / stable;
    if (lin == 0) out[OFF_PERP] = expf(-g_scal[1]);
}

// ---------------- launch ----------------
extern "C" void kernel_launch(void* const* d_in, const int* in_sizes, int n_in,
                              void* d_out, int out_size) {
    const float* x  = (const float*)d_in[0];   // [N, D]
    const float* e  = (const float*)d_in[1];   // [D, K]
    const float* cs = (const float*)d_in[2];   // [K]
    const float* un = (const float*)d_in[3];   // [D, K]
    float* out = (float*)d_out;

    prep_x_kernel<<<NTOK * 16 / 256, 256>>>(x);
    prep_e_kernel<<<KC / 256, 256>>>(e);
    coarse_kernel<<<NTOK / TM, 128, SMEM_DYN>>>();
    cleanup_kernel<<<dim3(192, KSPLIT), 256>>>(x, e);
    combine_kernel<<<64, 256>>>();
    quant_kernel<<<NTOK / 4, 256>>>(x, out);
    loss_kernel<<<1, 256>>>(out);
    newcs_kernel<<<KC / 256, 256>>>(cs, out);
    final_kernel<<<DIM * KC / 256, 256>>>(cs, un, out);
}